// round 14
// baseline (speedup 1.0000x reference)
#include <cuda_runtime.h>
#include <cstdint>

// QuantumCircuitLayer — TMA-bulk-staged, constant-bank params.
//
// R13: the 48B-strided LDG.128/STG.128 pattern amplifies L1 wavefronts 3x
// (each LDG touches 12 lines for 512B payload; L1 was the top pipe at 64.6%).
// Replace global IO with per-block 12KB cp.async.bulk (1D) in/out of smem;
// per-thread access becomes 48B-strided LDS/STS.128 which is CONFLICT-FREE
// (12-word stride covers all 32 banks across an 8-lane phase).
// Params stay in __constant__ (R12 win). Precompute now uses fast intrinsics.

#define PI_HALF 1.57079632679489662f

// Constant param layout:
//  [ 0.. 5]  -th0[q] = -0.5*rot[0,q,0]   (layer-0 rotation folded into phase)
//  [ 6..11]  c1[q]   [12..17] s1[q]   [18..23] -s1[q]
//  [24..29]  c2[q]   [30..35] s2[q]   [36..41] -s2[q]
//  [42..56]  t[l,j] = 0.5*sigmoid(ent[l,j])   (3 layers x 5)
//  [57..71]  1-t[l,j]
__constant__ float c_par[72];
__device__ float g_scratch[72];

__global__ void qc_precompute(const float* __restrict__ rot,
                              const float* __restrict__ ent) {
    int t = threadIdx.x;
    if (t >= 72) return;
    float v;
    if (t < 6)       v = -0.5f * rot[t * 3];
    else if (t < 12) v =  __cosf(0.5f * rot[(t)      * 3]);   // l1 c: (6+q)*3
    else if (t < 18) v =  __sinf(0.5f * rot[(t - 6)  * 3]);   // l1 s
    else if (t < 24) v = -__sinf(0.5f * rot[(t - 12) * 3]);   // l1 -s
    else if (t < 30) v =  __cosf(0.5f * rot[(t - 12) * 3]);   // l2 c: (12+q)*3
    else if (t < 36) v =  __sinf(0.5f * rot[(t - 18) * 3]);   // l2 s
    else if (t < 42) v = -__sinf(0.5f * rot[(t - 24) * 3]);   // l2 -s
    else if (t < 57) v = 0.5f / (1.0f + __expf(-ent[t - 42]));
    else             v = 1.0f - 0.5f / (1.0f + __expf(-ent[t - 57]));
    g_scratch[t] = v;
}

__device__ __forceinline__ float fsqrt_approx(float x) {
    float y;
    asm("sqrt.approx.f32 %0, %1;" : "=f"(y) : "f"(x));
    return y;
}

__device__ __forceinline__ uint32_t smem_u32(const void* p) {
    uint32_t a;
    asm("{ .reg .u64 t; cvta.to.shared.u64 t, %1; cvt.u32.u64 %0, t; }"
        : "=r"(a) : "l"(p));
    return a;
}

// One row: 6 in -> 6 out, params from constant bank.
__device__ __forceinline__ void qc_row(const float xin[6], float xout[6]) {
    float r[6], im[6];
#pragma unroll
    for (int q = 0; q < 6; q++) {
        float h = fmaf(xin[q], PI_HALF, c_par[q]);  // layer-0 rot folded
        r[q]  = __cosf(h);
        im[q] = __sinf(h);
    }
#pragma unroll
    for (int layer = 0; layer < 3; layer++) {
        if (layer > 0) {
            int cb = (layer == 1) ? 6 : 24;  // c at cb, s at cb+6, -s at cb+12
#pragma unroll
            for (int q = 0; q < 6; q++) {
                float c = c_par[cb + q], s = c_par[cb + 6 + q], ns = c_par[cb + 12 + q];
                float nr = fmaf(c, r[q],  s  * im[q]);
                float ni = fmaf(c, im[q], ns * r[q]);
                r[q] = nr; im[q] = ni;
            }
        }
        int tb = 42 + 5 * layer, ob = 57 + 5 * layer;
        float n0 = fmaf(c_par[ob + 0], r[0], c_par[tb + 0] * r[1]);
        float n1 = fmaf(c_par[ob + 1], r[1], c_par[tb + 1] * r[2]);
        float n2 = fmaf(c_par[ob + 2], r[2], c_par[tb + 2] * r[3]);
        float n3 = fmaf(c_par[ob + 3], r[3], c_par[tb + 3] * r[4]);
        float n4 = fmaf(c_par[ob + 4], r[4], c_par[tb + 4] * r[5]);
        float n5 = fmaf(c_par[ob + 4], r[5], c_par[tb + 4] * r[4]);
        r[0] = n0; r[1] = n1; r[2] = n2; r[3] = n3; r[4] = n4; r[5] = n5;
    }
#pragma unroll
    for (int q = 0; q < 6; q++)
        xout[q] = fsqrt_approx(fmaf(r[q], r[q], im[q] * im[q]));
}

// Tile: 256 threads x 2 rows x 6 floats = 3072 floats = 12288 bytes.
#define TILE_FLOATS 3072
#define TILE_BYTES  12288

__global__ void __launch_bounds__(256, 6)
qc_main(const float* __restrict__ x, float* __restrict__ out) {
    __shared__ __align__(128) float s_in[TILE_FLOATS];
    __shared__ __align__(128) float s_out[TILE_FLOATS];
    __shared__ __align__(8) unsigned long long s_mbar;

    int t = threadIdx.x;
    uint32_t in_a  = smem_u32(s_in);
    uint32_t out_a = smem_u32(s_out);
    uint32_t mbar  = smem_u32(&s_mbar);

    const char* gsrc = reinterpret_cast<const char*>(x) + (size_t)blockIdx.x * TILE_BYTES;
    char* gdst = reinterpret_cast<char*>(out) + (size_t)blockIdx.x * TILE_BYTES;

    if (t == 0) {
        asm volatile("mbarrier.init.shared.b64 [%0], %1;" :: "r"(mbar), "r"(1) : "memory");
    }
    __syncthreads();

    if (t == 0) {
        asm volatile("mbarrier.arrive.expect_tx.shared.b64 _, [%0], %1;"
                     :: "r"(mbar), "r"(TILE_BYTES) : "memory");
        asm volatile("cp.async.bulk.shared::cta.global.mbarrier::complete_tx::bytes "
                     "[%0], [%1], %2, [%3];"
                     :: "r"(in_a), "l"(gsrc), "r"(TILE_BYTES), "r"(mbar) : "memory");
    }

    // Wait (acquire) for the bulk load.
    {
        uint32_t done;
        asm volatile(
            "{\n\t.reg .pred p;\n\t"
            "mbarrier.try_wait.parity.acquire.cta.shared::cta.b64 p, [%1], 0;\n\t"
            "selp.b32 %0, 1, 0, p;\n\t}"
            : "=r"(done) : "r"(mbar) : "memory");
        if (!done) {
            asm volatile(
                "{\n\t.reg .pred P1;\n\t"
                "WL_%=:\n\t"
                "mbarrier.try_wait.parity.acquire.cta.shared::cta.b64 P1, [%0], 0, 0x989680;\n\t"
                "@P1 bra.uni WD_%=;\n\t"
                "bra.uni WL_%=;\n\t"
                "WD_%=:\n\t}"
                :: "r"(mbar) : "memory");
        }
    }

    // 2 rows/thread: floats [12t .. 12t+11] via 3 x LDS.128 (48B stride:
    // 12-word stride over 8-lane phases -> all 32 banks once, conflict-free).
    const float4* si4 = reinterpret_cast<const float4*>(s_in) + t * 3;
    float4 va = si4[0], vb = si4[1], vc = si4[2];

    float in0[6] = {va.x, va.y, va.z, va.w, vb.x, vb.y};
    float in1[6] = {vb.z, vb.w, vc.x, vc.y, vc.z, vc.w};
    float out0[6], out1[6];
    qc_row(in0, out0);
    qc_row(in1, out1);

    float4* so4 = reinterpret_cast<float4*>(s_out) + t * 3;
    so4[0] = make_float4(out0[0], out0[1], out0[2], out0[3]);
    so4[1] = make_float4(out0[4], out0[5], out1[0], out1[1]);
    so4[2] = make_float4(out1[2], out1[3], out1[4], out1[5]);

    __syncthreads();

    if (t == 0) {
        asm volatile("fence.proxy.async.shared::cta;" ::: "memory");
        asm volatile("cp.async.bulk.global.shared::cta.bulk_group [%0], [%1], %2;"
                     :: "l"(gdst), "r"(out_a), "r"(TILE_BYTES) : "memory");
        asm volatile("cp.async.bulk.commit_group;" ::: "memory");
        asm volatile("cp.async.bulk.wait_group 0;" ::: "memory");
    }
}

extern "C" void kernel_launch(void* const* d_in, const int* in_sizes, int n_in,
                              void* d_out, int out_size) {
    const float* x   = (const float*)d_in[0];  // [BATCH, 6] fp32
    const float* rot = (const float*)d_in[1];  // [3, 6, 3]  fp32
    const float* ent = (const float*)d_in[2];  // [3, 5]     fp32
    float* out = (float*)d_out;                // [BATCH, 6] fp32

    qc_precompute<<<1, 96>>>(rot, ent);

    void* scratch_ptr = nullptr;
    cudaGetSymbolAddress(&scratch_ptr, g_scratch);
    cudaMemcpyToSymbolAsync(c_par, scratch_ptr, 72 * sizeof(float), 0,
                            cudaMemcpyDeviceToDevice, 0);

    int total_floats = in_sizes[0];             // BATCH*6 = 25,165,824
    int n_tiles = total_floats / TILE_FLOATS;   // = 8192 (exact)
    qc_main<<<n_tiles, 256>>>(x, out);
}

// round 15
// speedup vs baseline: 1.1037x; 1.1037x over previous
#include <cuda_runtime.h>
#include <cstdint>

// QuantumCircuitLayer — f32x2-packed math + constant-bank duplicated-pair params.
//
// R14: R12/R13 proved the kernel is ISSUE-bound (~72% issue, L1 irrelevant:
// TMA variant cut L1 64.6->36% with zero speedup). Halve the FMA-pipe
// instruction stream by processing the thread's 2 rows as the 2 lanes of
// fma.rn.f32x2 / mul.rn.f32x2. R4's f32x2 attempt failed on smem-param LDS +
// packing movs; both are gone now: params are PRE-DUPLICATED 64-bit pairs in
// __constant__ (LDC.64, no LSU), and pack/unpack only brackets the scalar
// MUFU ops (sincos/sqrt), where ptxas folds them into register pairing.

#define PI_HALF 1.57079632679489662f

typedef unsigned long long u64;

// Packed-pair param layout (each u64 = duplicated float pair):
//  [ 0.. 5]  c1[q]    [ 6..11]  s1[q]   [12..17] -s1[q]
//  [18..23]  c2[q]    [24..29]  s2[q]   [30..35] -s2[q]
//  [36..50]  t[l,j]   = 0.5*sigmoid(ent[l,j])   (3 layers x 5)
//  [51..65]  1-t[l,j]
// th0[6] scalar = -0.5*rot[0,q,0]  (layer-0 rotation folded into phase)
struct Params { u64 pairs[66]; float th0[6]; };
__constant__ Params c_p;
__device__ Params g_scratch;

__device__ __forceinline__ u64 dup2(float a) {
    u64 r; asm("mov.b64 %0, {%1, %1};" : "=l"(r) : "f"(a)); return r;
}
__device__ __forceinline__ u64 pk2(float a, float b) {
    u64 r; asm("mov.b64 %0, {%1, %2};" : "=l"(r) : "f"(a), "f"(b)); return r;
}
__device__ __forceinline__ void upk2(float& a, float& b, u64 v) {
    asm("mov.b64 {%0, %1}, %2;" : "=f"(a), "=f"(b) : "l"(v));
}
__device__ __forceinline__ u64 fma2(u64 a, u64 b, u64 c) {
    u64 d; asm("fma.rn.f32x2 %0, %1, %2, %3;" : "=l"(d) : "l"(a), "l"(b), "l"(c)); return d;
}
__device__ __forceinline__ u64 mul2(u64 a, u64 b) {
    u64 d; asm("mul.rn.f32x2 %0, %1, %2;" : "=l"(d) : "l"(a), "l"(b)); return d;
}
__device__ __forceinline__ float fsqrt_approx(float x) {
    float y; asm("sqrt.approx.f32 %0, %1;" : "=f"(y) : "f"(x)); return y;
}

__global__ void qc_precompute(const float* __restrict__ rot,
                              const float* __restrict__ ent) {
    int t = threadIdx.x;
    if (t < 66) {
        float v;
        if (t < 6)       v =  __cosf(0.5f * rot[(6  + t)      * 3]);  // c1
        else if (t < 12) v =  __sinf(0.5f * rot[(6  + t - 6)  * 3]);  // s1
        else if (t < 18) v = -__sinf(0.5f * rot[(6  + t - 12) * 3]);  // -s1
        else if (t < 24) v =  __cosf(0.5f * rot[(12 + t - 18) * 3]);  // c2
        else if (t < 30) v =  __sinf(0.5f * rot[(12 + t - 24) * 3]);  // s2
        else if (t < 36) v = -__sinf(0.5f * rot[(12 + t - 30) * 3]);  // -s2
        else if (t < 51) v = 0.5f / (1.0f + __expf(-ent[t - 36]));    // t
        else             v = 1.0f - 0.5f / (1.0f + __expf(-ent[t - 51])); // 1-t
        g_scratch.pairs[t] = dup2(v);
    } else if (t < 72) {
        g_scratch.th0[t - 66] = -0.5f * rot[(t - 66) * 3];
    }
}

__global__ void __launch_bounds__(256, 5)
qc_main(const float* __restrict__ x, float* __restrict__ out, int n_threads) {
    int tid = blockIdx.x * 256 + threadIdx.x;
    if (tid >= n_threads) return;

    // 2 rows/thread = 12 floats = 3 float4 (48B stride, 16B aligned).
    const float4* xin = reinterpret_cast<const float4*>(x) + (size_t)tid * 3;
    float4* o4 = reinterpret_cast<float4*>(out) + (size_t)tid * 3;

    float4 va = __ldcs(xin + 0);
    float4 vb = __ldcs(xin + 1);
    float4 vc = __ldcs(xin + 2);
    float b0[6] = {va.x, va.y, va.z, va.w, vb.x, vb.y};   // row 0
    float b1[6] = {vb.z, vb.w, vc.x, vc.y, vc.z, vc.w};   // row 1

    const u64* P = c_p.pairs;

    u64 r[6], im[6];

    // init (scalar h + MUFU, packed results): h = x*pi/2 - th0
#pragma unroll
    for (int q = 0; q < 6; q++) {
        float h0 = fmaf(b0[q], PI_HALF, c_p.th0[q]);
        float h1 = fmaf(b1[q], PI_HALF, c_p.th0[q]);
        r[q]  = pk2(__cosf(h0), __cosf(h1));
        im[q] = pk2(__sinf(h0), __sinf(h1));
    }

#pragma unroll
    for (int layer = 0; layer < 3; layer++) {
        if (layer > 0) {
            int cb = (layer == 1) ? 0 : 18;  // c at cb, s at cb+6, -s at cb+12
#pragma unroll
            for (int q = 0; q < 6; q++) {
                u64 nr = fma2(P[cb + q], r[q],  mul2(P[cb + 6 + q],  im[q]));
                u64 ni = fma2(P[cb + q], im[q], mul2(P[cb + 12 + q], r[q]));
                r[q] = nr; im[q] = ni;
            }
        }
        // entangle, snapshot semantics: n_q = (1-t_q)*r_q + t_q*r_{q+1}, q<5
        //                               n_5 = (1-t_4)*r_5 + t_4*r_4
        int tb = 36 + 5 * layer, ob = 51 + 5 * layer;
        u64 n0 = fma2(P[ob + 0], r[0], mul2(P[tb + 0], r[1]));
        u64 n1 = fma2(P[ob + 1], r[1], mul2(P[tb + 1], r[2]));
        u64 n2 = fma2(P[ob + 2], r[2], mul2(P[tb + 2], r[3]));
        u64 n3 = fma2(P[ob + 3], r[3], mul2(P[tb + 3], r[4]));
        u64 n4 = fma2(P[ob + 4], r[4], mul2(P[tb + 4], r[5]));
        u64 n5 = fma2(P[ob + 4], r[5], mul2(P[tb + 4], r[4]));
        r[0] = n0; r[1] = n1; r[2] = n2; r[3] = n3; r[4] = n4; r[5] = n5;
    }

    // magnitude: packed |.|^2, scalar sqrt per lane
#pragma unroll
    for (int q = 0; q < 6; q++) {
        u64 m2 = fma2(r[q], r[q], mul2(im[q], im[q]));
        float m0, m1;
        upk2(m0, m1, m2);
        b0[q] = fsqrt_approx(m0);
        b1[q] = fsqrt_approx(m1);
    }

    __stcs(o4 + 0, make_float4(b0[0], b0[1], b0[2], b0[3]));
    __stcs(o4 + 1, make_float4(b0[4], b0[5], b1[0], b1[1]));
    __stcs(o4 + 2, make_float4(b1[2], b1[3], b1[4], b1[5]));
}

extern "C" void kernel_launch(void* const* d_in, const int* in_sizes, int n_in,
                              void* d_out, int out_size) {
    const float* x   = (const float*)d_in[0];  // [BATCH, 6] fp32
    const float* rot = (const float*)d_in[1];  // [3, 6, 3]  fp32
    const float* ent = (const float*)d_in[2];  // [3, 5]     fp32
    float* out = (float*)d_out;                // [BATCH, 6] fp32

    qc_precompute<<<1, 96>>>(rot, ent);

    void* scratch_ptr = nullptr;
    cudaGetSymbolAddress(&scratch_ptr, g_scratch);
    cudaMemcpyToSymbolAsync(c_p, scratch_ptr, sizeof(Params), 0,
                            cudaMemcpyDeviceToDevice, 0);

    int total_floats = in_sizes[0];            // BATCH * 6 (divisible by 12)
    int n_threads = total_floats / 12;         // 2 rows per thread
    int blocks = (n_threads + 255) / 256;
    qc_main<<<blocks, 256>>>(x, out, n_threads);
}